// round 6
// baseline (speedup 1.0000x reference)
#include <cuda_runtime.h>
#include <cuda_fp16.h>
#include <cstdint>

// MoE SwiGLU via fp16 tensor cores (mma.m16n8k16, fp32 accum), fused
// fp32->fp16 conversion in the smem load path. Weights stay fp32 in HBM.
// R5: 512 threads / 16 warps per CTA (was 256/8) -> 50% occupancy, halved
// warp tiles (acc 64/16 floats) so everything fits in 128 regs/thread.
//   1) route_kernel : bucket 1024 (token,slot) pairs by expert
//   2) gemm1_kernel : hbuf(fp16) = silu(x.w1[e]^T) * (x.w3[e]^T)
//   3) gemm2_kernel : out = hbuf . w2[e]   (fp32 out)

namespace {
constexpr int kE = 8;
constexpr int kTOPK = 2;
constexpr int kH = 2816;
constexpr int kD = 1024;
constexpr int NP = 1024;

// GEMM1: BM=128 tokens, BN=128 h (x2 matrices), BK=16
constexpr int G1_NT_H = kH / 128;       // 22 h-tiles
constexpr int G1_XS = 24;               // smem row stride fp16 (16+8 pad, 12w%8=4)
// GEMM2: BM=128 tokens, BN=64 d, BK=32
constexpr int G2_NT_D = kD / 64;        // 16 d-tiles
constexpr int G2_AS = 40;               // A row stride fp16 (32+8 pad, 20w%8=4)
constexpr int G2_BS = 72;               // B row stride fp16 (64+8 pad, 36w%8=4)
}

__device__ int    g_off[kE + 1];
__device__ int    g_pairs[NP];
__device__ __half g_hbuf[(size_t)NP * kH];   // 5.77 MB fp16 intermediate

// ---------------------------------------------------------------------------
// helpers
// ---------------------------------------------------------------------------
__device__ __forceinline__ uint32_t s2u(const void* p) {
    return (uint32_t)__cvta_generic_to_shared(p);
}
__device__ __forceinline__ void ldsm_x4(uint32_t r[4], uint32_t addr) {
    asm volatile("ldmatrix.sync.aligned.m8n8.x4.shared.b16 {%0,%1,%2,%3}, [%4];"
                 : "=r"(r[0]), "=r"(r[1]), "=r"(r[2]), "=r"(r[3]) : "r"(addr));
}
__device__ __forceinline__ void ldsm_x4_t(uint32_t r[4], uint32_t addr) {
    asm volatile("ldmatrix.sync.aligned.m8n8.x4.trans.shared.b16 {%0,%1,%2,%3}, [%4];"
                 : "=r"(r[0]), "=r"(r[1]), "=r"(r[2]), "=r"(r[3]) : "r"(addr));
}
__device__ __forceinline__ void mma16816(float c[4], const uint32_t a[4],
                                         uint32_t b0, uint32_t b1) {
    asm volatile(
        "mma.sync.aligned.m16n8k16.row.col.f32.f16.f16.f32 "
        "{%0,%1,%2,%3},{%4,%5,%6,%7},{%8,%9},{%0,%1,%2,%3};"
        : "+f"(c[0]), "+f"(c[1]), "+f"(c[2]), "+f"(c[3])
        : "r"(a[0]), "r"(a[1]), "r"(a[2]), "r"(a[3]), "r"(b0), "r"(b1));
}
__device__ __forceinline__ uint32_t h2u(__half2 h) {
    return *reinterpret_cast<uint32_t*>(&h);
}
__device__ __forceinline__ uint2 cvt4(float4 v) {
    uint2 u = { h2u(__floats2half2_rn(v.x, v.y)),
                h2u(__floats2half2_rn(v.z, v.w)) };
    return u;
}
__device__ __forceinline__ float silu(float z) {
    return z / (1.0f + __expf(-z));
}

// ---------------------------------------------------------------------------
// Routing (int32/int64 dtype auto-detect, validated in R3/R4)
// ---------------------------------------------------------------------------
__global__ void route_kernel(const void* __restrict__ eidx_raw) {
    __shared__ int cnt[kE];
    __shared__ int cur[kE];
    __shared__ int not64;
    int tid = threadIdx.x;
    if (tid < kE) cnt[tid] = 0;
    if (tid == 0) not64 = 0;
    __syncthreads();

    const long long* p64 = (const long long*)eidx_raw;
    if (tid < NP / 2) {
        long long v = p64[tid];
        if (v < 0 || v >= kE) not64 = 1;
    }
    __syncthreads();

    int e = not64 ? ((const int*)eidx_raw)[tid] : (int)p64[tid];

    atomicAdd(&cnt[e], 1);
    __syncthreads();
    if (tid == 0) {
        int o = 0;
        for (int i = 0; i < kE; i++) { g_off[i] = o; cur[i] = o; o += cnt[i]; }
        g_off[kE] = o;
    }
    __syncthreads();
    int p = atomicAdd(&cur[e], 1);
    g_pairs[p] = tid;
}

// ---------------------------------------------------------------------------
// GEMM1 + SwiGLU (fp16 HMMA), 512 threads.
// grid.x = 2 strips * 22 htiles * 8 experts = 352 (strip fastest -> L2 share)
// Block tile: 128 tokens x 128 h (both w1 and w3), K=1024 in 64 stages of 16.
// 16 warps: 4 (m) x 4 (n); warp tile 32m x 32n per matrix. acc = 64 floats.
// ---------------------------------------------------------------------------
__global__ __launch_bounds__(512, 1)
void gemm1_kernel(const float* __restrict__ x,
                  const float* __restrict__ w1,
                  const float* __restrict__ w3) {
    __shared__ __half Xs [2][128][G1_XS];
    __shared__ __half W1s[2][128][G1_XS];
    __shared__ __half W3s[2][128][G1_XS];
    __shared__ int    toks[128];

    const int bx    = blockIdx.x;
    const int strip = bx & 1;
    const int ht    = (bx >> 1) % G1_NT_H;
    const int e     = bx / (2 * G1_NT_H);
    const int hb    = ht * 128;
    const int base  = g_off[e];
    const int nt    = g_off[e + 1] - base;

    const int tid  = threadIdx.x;
    const int lane = tid & 31;
    const int wid  = tid >> 5;
    const int wm   = wid & 3;       // 4 m-warps (32 rows each)
    const int wn   = wid >> 2;      // 4 n-warps (32 cols each)

    const float* w1e = w1 + ((size_t)e * kH + hb) * kD;
    const float* w3e = w3 + ((size_t)e * kH + hb) * kD;

    const int lrow = lane & 15;
    const int lcol = (lane >> 4) * 8;

    // per-stage load coords: 512 threads cover 128 rows x 4 float4 exactly
    const int lm = tid >> 2;        // row 0..127
    const int lk = (tid & 3) * 4;   // col 0,4,8,12

    for (int t0 = strip * 128; t0 < nt; t0 += 256) {
        const int ntt = min(128, nt - t0);

        if (tid < 128)
            toks[tid] = g_pairs[base + t0 + min(tid, ntt - 1)] / kTOPK;
        __syncthreads();

        float4 st[3];
        auto ldg_stage = [&](int d0) {
            st[0] = *(const float4*)&x[(size_t)toks[lm] * kD + d0 + lk];
            st[1] = *(const float4*)&w1e[(size_t)lm * kD + d0 + lk];
            st[2] = *(const float4*)&w3e[(size_t)lm * kD + d0 + lk];
        };
        auto sts_stage = [&](int s) {
            *(uint2*)&Xs [s][lm][lk] = cvt4(st[0]);
            *(uint2*)&W1s[s][lm][lk] = cvt4(st[1]);
            *(uint2*)&W3s[s][lm][lk] = cvt4(st[2]);
        };

        ldg_stage(0);
        sts_stage(0);
        __syncthreads();

        float acc1[2][4][4], acc3[2][4][4];
        #pragma unroll
        for (int mt = 0; mt < 2; mt++)
            #pragma unroll
            for (int ntl = 0; ntl < 4; ntl++)
                #pragma unroll
                for (int q = 0; q < 4; q++) { acc1[mt][ntl][q] = 0.f; acc3[mt][ntl][q] = 0.f; }

        const int NST = kD / 16;   // 64
        for (int ks = 0; ks < NST; ks++) {
            int s = ks & 1;
            if (ks + 1 < NST) ldg_stage((ks + 1) * 16);

            uint32_t a[2][4], b1[2][4], b3[2][4];
            #pragma unroll
            for (int mt = 0; mt < 2; mt++)
                ldsm_x4(a[mt], s2u(&Xs[s][wm * 32 + mt * 16 + lrow][lcol]));
            #pragma unroll
            for (int g2 = 0; g2 < 2; g2++) {
                ldsm_x4(b1[g2], s2u(&W1s[s][wn * 32 + g2 * 16 + lrow][lcol]));
                ldsm_x4(b3[g2], s2u(&W3s[s][wn * 32 + g2 * 16 + lrow][lcol]));
            }
            #pragma unroll
            for (int mt = 0; mt < 2; mt++)
                #pragma unroll
                for (int ntl = 0; ntl < 4; ntl++) {
                    int g2 = ntl >> 1, sub = ntl & 1;
                    mma16816(acc1[mt][ntl], a[mt], b1[g2][sub], b1[g2][2 + sub]);
                    mma16816(acc3[mt][ntl], a[mt], b3[g2][sub], b3[g2][2 + sub]);
                }

            if (ks + 1 < NST) sts_stage(s ^ 1);
            __syncthreads();
        }

        // epilogue: silu(h1)*h3 -> g_hbuf (fp16)
        #pragma unroll
        for (int mt = 0; mt < 2; mt++) {
            int row0 = wm * 32 + mt * 16 + (lane >> 2);
            #pragma unroll
            for (int ntl = 0; ntl < 4; ntl++) {
                int col = hb + wn * 32 + ntl * 8 + (lane & 3) * 2;
                if (row0 < ntt) {
                    float v0 = silu(acc1[mt][ntl][0]) * acc3[mt][ntl][0];
                    float v1 = silu(acc1[mt][ntl][1]) * acc3[mt][ntl][1];
                    *(__half2*)&g_hbuf[(size_t)(base + t0 + row0) * kH + col] =
                        __floats2half2_rn(v0, v1);
                }
                if (row0 + 8 < ntt) {
                    float v0 = silu(acc1[mt][ntl][2]) * acc3[mt][ntl][2];
                    float v1 = silu(acc1[mt][ntl][3]) * acc3[mt][ntl][3];
                    *(__half2*)&g_hbuf[(size_t)(base + t0 + row0 + 8) * kH + col] =
                        __floats2half2_rn(v0, v1);
                }
            }
        }
        __syncthreads();
    }
}

// ---------------------------------------------------------------------------
// GEMM2 (fp16 HMMA), 512 threads: out[pair, d] = hbuf[p, :] . w2[e, :, d]
// grid.x = 2 strips * 16 dtiles * 8 experts = 256
// Block tile: 128 tokens x 64 d, K=2816 in 88 stages of 32.
// 16 warps: 4 (m) x 4 (n); warp tile 32m x 16n. acc = 16 floats.
// ---------------------------------------------------------------------------
__global__ __launch_bounds__(512, 1)
void gemm2_kernel(const float* __restrict__ w2, float* __restrict__ out) {
    __shared__ __half As[2][128][G2_AS];
    __shared__ __half Bs[2][32][G2_BS];
    __shared__ int    prs[128];

    const int bx    = blockIdx.x;
    const int strip = bx & 1;
    const int dt    = (bx >> 1) % G2_NT_D;
    const int e     = bx / (2 * G2_NT_D);
    const int ib    = dt * 64;
    const int base  = g_off[e];
    const int nt    = g_off[e + 1] - base;

    const int tid  = threadIdx.x;
    const int lane = tid & 31;
    const int wid  = tid >> 5;
    const int wm   = wid & 3;       // 4 m-warps (32 rows)
    const int wn   = wid >> 2;      // 4 n-warps (16 cols)

    const float* w2e = w2 + (size_t)e * kH * kD + ib;

    const int lrow = lane & 15;
    const int lcol = (lane >> 4) * 8;
    // trans-ldmatrix coords for B (16k x 16n tile)
    const int ti   = lane >> 3;
    const int trow = (ti >> 1) * 8 + (lane & 7);
    const int tcol = (ti & 1) * 8;

    // per-stage load coords
    const int am = tid >> 2;          // A: row 0..127
    const int ak = (tid & 3) * 8;     // A: 4 x uint4 (8 halves)
    const int bh = tid >> 4;          // B: row 0..31
    const int bd = (tid & 15) * 4;    // B: 16 x float4

    for (int t0 = strip * 128; t0 < nt; t0 += 256) {
        const int ntt = min(128, nt - t0);

        if (tid < 128)
            prs[tid] = g_pairs[base + t0 + min(tid, ntt - 1)];
        __syncthreads();

        const int arow = min(am, ntt - 1);

        uint4  stA;
        float4 stB;
        auto ldg_stage = [&](int h0) {
            stA = *(const uint4*)&g_hbuf[(size_t)(base + t0 + arow) * kH + h0 + ak];
            stB = *(const float4*)&w2e[(size_t)(h0 + bh) * kD + bd];
        };
        auto sts_stage = [&](int s) {
            *(uint4*)&As[s][am][ak] = stA;
            *(uint2*)&Bs[s][bh][bd] = cvt4(stB);
        };

        ldg_stage(0);
        sts_stage(0);
        __syncthreads();

        float acc[2][2][4];
        #pragma unroll
        for (int mt = 0; mt < 2; mt++)
            #pragma unroll
            for (int ntl = 0; ntl < 2; ntl++)
                #pragma unroll
                for (int q = 0; q < 4; q++) acc[mt][ntl][q] = 0.f;

        const int NST = kH / 32;   // 88
        for (int ks = 0; ks < NST; ks++) {
            int s = ks & 1;
            if (ks + 1 < NST) ldg_stage((ks + 1) * 32);

            #pragma unroll
            for (int kk = 0; kk < 2; kk++) {
                uint32_t a[2][4], b[4];
                #pragma unroll
                for (int mt = 0; mt < 2; mt++)
                    ldsm_x4(a[mt], s2u(&As[s][wm * 32 + mt * 16 + lrow][kk * 16 + lcol]));
                ldsm_x4_t(b, s2u(&Bs[s][kk * 16 + trow][wn * 16 + tcol]));
                #pragma unroll
                for (int mt = 0; mt < 2; mt++)
                    #pragma unroll
                    for (int ntl = 0; ntl < 2; ntl++)
                        mma16816(acc[mt][ntl], a[mt], b[ntl], b[2 + ntl]);
            }

            if (ks + 1 < NST) sts_stage(s ^ 1);
            __syncthreads();
        }

        // epilogue: fp32 stores to out[pair][d]
        #pragma unroll
        for (int mt = 0; mt < 2; mt++) {
            int row0 = wm * 32 + mt * 16 + (lane >> 2);
            #pragma unroll
            for (int ntl = 0; ntl < 2; ntl++) {
                int col = ib + wn * 16 + ntl * 8 + (lane & 3) * 2;
                if (row0 < ntt) {
                    float2 v = { acc[mt][ntl][0], acc[mt][ntl][1] };
                    *(float2*)&out[(size_t)prs[row0] * kD + col] = v;
                }
                if (row0 + 8 < ntt) {
                    float2 v = { acc[mt][ntl][2], acc[mt][ntl][3] };
                    *(float2*)&out[(size_t)prs[row0 + 8] * kD + col] = v;
                }
            }
        }
        __syncthreads();
    }
}

// ---------------------------------------------------------------------------
extern "C" void kernel_launch(void* const* d_in, const int* in_sizes, int n_in,
                              void* d_out, int out_size) {
    const float* x    = (const float*)d_in[0];
    const void*  eidx = d_in[1];
    const float* w1   = (const float*)d_in[2];
    const float* w2   = (const float*)d_in[3];
    const float* w3   = (const float*)d_in[4];
    float*       out  = (float*)d_out;

    route_kernel<<<1, NP>>>(eidx);
    gemm1_kernel<<<2 * G1_NT_H * kE, 512>>>(x, w1, w3);
    gemm2_kernel<<<2 * G2_NT_D * kE, 512>>>(w2, out);
}